// round 4
// baseline (speedup 1.0000x reference)
#include <cuda_runtime.h>
#include <cuda_fp16.h>

// DifferentiableCensus: out = (1/9) * sum_{3x3, edge-clamped} sigmoid(neighbor - center)
// x: (16,3,512,512) f32 -> 48 independent 512x512 images.
//
// Round 4: issue/latency-bound -> full half2 SIMD datapath.
//  - Rows stored as half2 (prescaled by 0.5), diffs via HSUB2, tanh.approx.f16x2,
//    signed edge-sharing sums in half2 with PRMT lane realignment.
//  - f32 only at load (pack) and final FMA/store.
//  - 4 cols x 8 rows per thread; every pixel-pair edge computed once
//    (reverse term = negation via sigmoid antisymmetry).

static constexpr int H = 512;
static constexpr int W = 512;
static constexpr int ROWS_PER_THREAD = 8;
static constexpr int BLOCK_X = 128;            // 128 threads * 4 cols = 512 cols

__device__ __forceinline__ __half2 tanh_h2(__half2 h) {
    unsigned u = *reinterpret_cast<unsigned*>(&h);
    unsigned r;
    asm("tanh.approx.f16x2 %0, %1;" : "=r"(r) : "r"(u));
    return *reinterpret_cast<__half2*>(&r);
}

__device__ __forceinline__ __half2 prmt(__half2 a, __half2 b, unsigned sel) {
    unsigned r = __byte_perm(*reinterpret_cast<unsigned*>(&a),
                             *reinterpret_cast<unsigned*>(&b), sel);
    return *reinterpret_cast<__half2*>(&r);
}
// sel cheat sheet (lane = 16-bit half; lo = lane0):
//  (a.lo, b.lo) = 0x5410   (a.hi, b.lo) = 0x5432
//  (a.hi, a.hi) = 0x3232   (a.lo, a.lo) = 0x1010   swap(a) = 0x1032

struct RowH2 { __half2 A, B, C; };   // (v0,v1),(v2,v3),(v4,v5); v0/v5 = clamped halo

__device__ __forceinline__ RowH2 load_row(const float* __restrict__ row,
                                          int c0, int cl, int cr) {
    const float4 m = __ldg(reinterpret_cast<const float4*>(row + c0));
    const float  l = __ldg(row + cl);
    const float  r = __ldg(row + cr);
    const __half2 hhalf = __float2half2_rn(0.5f);
    RowH2 o;
    o.A = __hmul2(__floats2half2_rn(l,   m.x), hhalf);
    o.B = __hmul2(__floats2half2_rn(m.y, m.z), hhalf);
    o.C = __hmul2(__floats2half2_rn(m.w, r  ), hhalf);
    return o;
}

__global__ __launch_bounds__(BLOCK_X)
void census_kernel(const float* __restrict__ x, float* __restrict__ out) {
    const int c0  = threadIdx.x * 4;
    const int r0  = blockIdx.y * ROWS_PER_THREAD;
    const int img = blockIdx.z;

    const float* __restrict__ xi = x   + (size_t)img * H * W;
    float* __restrict__       oi = out + (size_t)img * H * W;

    const int cl = max(c0 - 1, 0);
    const int cr = min(c0 + 4, W - 1);

    RowH2 p = load_row(xi + (size_t)max(r0 - 1, 0) * W, c0, cl, cr);
    RowH2 b = load_row(xi + (size_t)r0 * W,             c0, cl, cr);

    __half2 bc1 = prmt(b.A, b.B, 0x5432);   // (b1,b2) centers
    __half2 bc2 = prmt(b.B, b.C, 0x5432);   // (b3,b4)

    // Priming carries: S/SE/SW edge tanh of row r0-1 (r0==0 -> tanh(0)=0).
    __half2 pc1 = prmt(p.A, p.B, 0x5432);
    __half2 pc2 = prmt(p.B, p.C, 0x5432);
    __half2 pSa  = tanh_h2(__hsub2(bc1, pc1)), pSb  = tanh_h2(__hsub2(bc2, pc2));
    __half2 pDRa = tanh_h2(__hsub2(b.B, pc1)), pDRb = tanh_h2(__hsub2(b.C, pc2));
    __half2 pDLa = tanh_h2(__hsub2(b.A, pc1)), pDLb = tanh_h2(__hsub2(b.B, pc2));
    __half2 pA = p.A, pC = p.C;             // only halo lanes of p needed later

    const __half2 zero = __float2half2_rn(0.0f);

    #pragma unroll
    for (int k = 0; k < ROWS_PER_THREAD; k++) {
        const int r = r0 + k;
        RowH2 n = load_row(xi + (size_t)min(r + 1, H - 1) * W, c0, cl, cr);
        __half2 nc1 = prmt(n.A, n.B, 0x5432);
        __half2 nc2 = prmt(n.B, n.C, 0x5432);

        // Forward edges of this row (2 tanh per MUFU issue).
        __half2 Sa  = tanh_h2(__hsub2(nc1, bc1)), Sb  = tanh_h2(__hsub2(nc2, bc2));
        __half2 DRa = tanh_h2(__hsub2(n.B, bc1)), DRb = tanh_h2(__hsub2(n.C, bc2));
        __half2 DLa = tanh_h2(__hsub2(n.A, bc1)), DLb = tanh_h2(__hsub2(n.B, bc2));
        __half2 Ea  = tanh_h2(__hsub2(b.B, bc1)), Eb  = tanh_h2(__hsub2(b.C, bc2));

        // Halo edges: (W0, UL0) and (UR3, UR3).
        __half2 H1 = tanh_h2(__hsub2(prmt(b.A, pA, 0x5410),   // (b0, p0)
                                     prmt(b.A, b.A, 0x3232)));// (b1, b1)
        __half2 H2 = tanh_h2(__hsub2(prmt(pC, pC, 0x3232),    // (p5, p5)
                                     prmt(b.C, b.C, 0x1010)));// (b4, b4)

        // Aligned part: S + DR + DL - pS + E.
        __half2 al1 = __hadd2(__hadd2(Sa, DRa), __hsub2(DLa, pSa));
        __half2 al2 = __hadd2(__hadd2(Sb, DRb), __hsub2(DLb, pSb));
        al1 = __hadd2(al1, Ea);
        al2 = __hadd2(al2, Eb);

        // Misaligned part:
        //  X = (W0+UL0 - pDL1,  -E0 - pDR0 - pDL2,  -E1 - pDR1 - pDL3,  -E2 - pDR2 + UR3)
        __half2 sWU  = __hadd2(H1, prmt(H1, H1, 0x1032));     // both lanes = W0+UL0
        __half2 nEa  = __hneg2(Ea);
        __half2 nEb  = __hneg2(Eb);
        __half2 nUR  = __hneg2(H2);
        __half2 Alo  = prmt(sWU, nEa, 0x5410);                // (W0+UL0, -E0)
        __half2 Ahi  = prmt(nEa, nEb, 0x5432);                // (-E1, -E2)
        __half2 Blo  = prmt(zero, pDRa, 0x5410);              // (0, pDR0)
        __half2 Bhi  = prmt(pDRa, pDRb, 0x5432);              // (pDR1, pDR2)
        __half2 Clo  = prmt(pDLa, pDLb, 0x5432);              // (pDL1, pDL2)
        __half2 Chi  = prmt(pDLb, nUR, 0x5432);               // (pDL3, -UR3)

        __half2 Tlo = __hadd2(al1, __hsub2(__hsub2(Alo, Blo), Clo));
        __half2 Thi = __hadd2(al2, __hsub2(__hsub2(Ahi, Bhi), Chi));

        const float2 lo = __half22float2(Tlo);
        const float2 hi = __half22float2(Thi);
        float4 o;
        o.x = fmaf(lo.x, 1.0f / 18.0f, 0.5f);
        o.y = fmaf(lo.y, 1.0f / 18.0f, 0.5f);
        o.z = fmaf(hi.x, 1.0f / 18.0f, 0.5f);
        o.w = fmaf(hi.y, 1.0f / 18.0f, 0.5f);
        *reinterpret_cast<float4*>(oi + (size_t)r * W + c0) = o;

        // Roll rows and carries.
        pA = b.A; pC = b.C;
        b = n; bc1 = nc1; bc2 = nc2;
        pSa = Sa; pSb = Sb;
        pDRa = DRa; pDRb = DRb;
        pDLa = DLa; pDLb = DLb;
    }
}

extern "C" void kernel_launch(void* const* d_in, const int* in_sizes, int n_in,
                              void* d_out, int out_size) {
    (void)in_sizes; (void)n_in; (void)out_size;
    const float* x = (const float*)d_in[0];
    float* out = (float*)d_out;

    dim3 block(BLOCK_X, 1, 1);
    dim3 grid(1, H / ROWS_PER_THREAD, 16 * 3);
    census_kernel<<<grid, block>>>(x, out);
}